// round 1
// baseline (speedup 1.0000x reference)
#include <cuda_runtime.h>
#include <math.h>

#define D 256
#define HH 512
#define MT 32            // rows per CTA
#define NTHREADS 512
#define XSTR 34          // padded row stride (floats) for smem tiles
#define MAX_NODES 65536
#define MAX_LVL 16384

// Scratch (static __device__ — no runtime allocation)
__device__ float g_embeds[MAX_NODES * D];
__device__ int   g_list[6][MAX_LVL];   // slots: t2,b2,t1,b1,t0,b0 (row indices within level)
__device__ int   g_cnt[6];

// ---------------- small helpers ----------------
__device__ __forceinline__ unsigned long long pack2(float a) {
    unsigned long long r;
    asm("mov.b64 %0, {%1, %1};" : "=l"(r) : "f"(a));
    return r;
}
__device__ __forceinline__ void fma2(unsigned long long &acc, unsigned long long w, unsigned long long x) {
    asm("fma.rn.f32x2 %0, %1, %2, %0;" : "+l"(acc) : "l"(w), "l"(x));
}
__device__ __forceinline__ float2 unpack2(unsigned long long v) {
    float lo, hi;
    asm("mov.b64 {%0, %1}, %2;" : "=f"(lo), "=f"(hi) : "l"(v));
    return make_float2(lo, hi);
}
__device__ __forceinline__ float gelu_exact(float x) {
    return 0.5f * x * (1.0f + erff(x * 0.70710678118654752440f));
}

// ---------------- init: node_embeds = comp_table[comp_ids] ----------------
__global__ void init_embeds_kernel(const int* __restrict__ comp_ids,
                                   const float* __restrict__ comp_table) {
    int node = blockIdx.x;
    int c = threadIdx.x;
    g_embeds[node * D + c] = comp_table[comp_ids[node] * D + c];
}

__global__ void reset_kernel() {
    if (threadIdx.x < 6) g_cnt[threadIdx.x] = 0;
}

// Partition each level's rows into ternary / binary lists.
__global__ void compact_kernel(const int* __restrict__ lvl2, int n2,
                               const int* __restrict__ lvl1, int n1,
                               const int* __restrict__ lvl0, int n0,
                               const int* __restrict__ third) {
    int i = blockIdx.x * blockDim.x + threadIdx.x;
    int lvl, j;
    const int* idx;
    if (i < n2)              { lvl = 0; j = i;           idx = lvl2; }
    else if (i < n2 + n1)    { lvl = 1; j = i - n2;      idx = lvl1; }
    else if (i < n2 + n1 + n0){ lvl = 2; j = i - n2 - n1; idx = lvl0; }
    else return;
    int node = idx[j];
    bool tern = (third[node] >= 0);
    int slot = lvl * 2 + (tern ? 0 : 1);
    int pos = atomicAdd(&g_cnt[slot], 1);
    g_list[slot][pos] = j;
}

// ---------------- fused level kernel ----------------
// smem: [256 floats meta][xs: 1024*XSTR][hs: 512*XSTR]
#define SMEM_FLOATS (256 + 1024 * XSTR + 512 * XSTR)
#define SMEM_BYTES  (SMEM_FLOATS * 4)

__global__ __launch_bounds__(NTHREADS, 1)
void level_kernel(int nbt, int lvl_slot,
                  const int* __restrict__ lvl_idx,
                  const int* __restrict__ lc, const int* __restrict__ rc,
                  const int* __restrict__ tcld,
                  const int* __restrict__ opids,
                  const float* __restrict__ op_table,
                  const float* __restrict__ W1b, const float* __restrict__ b1b,
                  const float* __restrict__ W2b, const float* __restrict__ b2b,
                  const float* __restrict__ W1t, const float* __restrict__ b1t,
                  const float* __restrict__ W2t, const float* __restrict__ b2t,
                  const float* __restrict__ gma, const float* __restrict__ bta,
                  float* __restrict__ final_out) {
    extern __shared__ float smem[];
    int* meta = (int*)smem;                 // [0..31]=node, [32..63]=i, [64..95]=valid
    float* xs = smem + 256;                 // [k][m] stride XSTR
    float* hs = xs + 1024 * XSTR;           // [c][m] stride XSTR (also zbuf)

    bool tern = (blockIdx.x < nbt);
    int slot = lvl_slot * 2 + (tern ? 0 : 1);
    int cnt = g_cnt[slot];
    int blk = tern ? blockIdx.x : (blockIdx.x - nbt);
    int base = blk * MT;
    if (base >= cnt) return;

    const int* rows = g_list[slot];
    const int K1 = tern ? 1024 : 768;
    const float* W1 = tern ? W1t : W1b;
    const float* B1 = tern ? b1t : b1b;
    const float* W2 = tern ? W2t : W2b;
    const float* B2 = tern ? b2t : b2b;

    int t = threadIdx.x;

    // ---- gather x tile ----
    {
        int m = t >> 4, q = t & 15;
        int rr = min(base + m, cnt - 1);
        int i = rows[rr];
        int node = lvl_idx[i];
        if (q == 0) {
            meta[m] = node;
            meta[32 + m] = i;
            meta[64 + m] = (base + m < cnt) ? 1 : 0;
        }
        int ln = lc[node], rn = rc[node];
        const float* src0 = op_table + opids[node] * D;
        const float* src1 = g_embeds + ln * D;
        const float* src2 = g_embeds + rn * D;
        const float* src3 = tern ? (g_embeds + tcld[node] * D) : src1;
        const float* srcs[4] = {src0, src1, src2, src3};
        int nseg = tern ? 4 : 3;
        for (int s = 0; s < nseg; s++) {
            const float4* sp = (const float4*)srcs[s];
            #pragma unroll
            for (int kk = q; kk < 64; kk += 16) {
                float4 v = sp[kk];
                int kb = s * 256 + kk * 4;
                xs[(kb + 0) * XSTR + m] = v.x;
                xs[(kb + 1) * XSTR + m] = v.y;
                xs[(kb + 2) * XSTR + m] = v.z;
                xs[(kb + 3) * XSTR + m] = v.w;
            }
        }
    }
    __syncthreads();

    int cg = t & 127, rg = t >> 7;

    // ---- GEMM1: h = gelu(x @ W1 + b1), 4 cols x 8 rows per thread ----
    {
        int c0 = cg * 4, r0 = rg * 8;
        unsigned long long acc[16];
        #pragma unroll
        for (int z = 0; z < 16; z++) acc[z] = 0ULL;

        const float4* W1v = (const float4*)W1;   // [k][HH/4]
        int widx = c0 >> 2;

        float4 wa = W1v[widx];
        float4 wb = W1v[(HH / 4) + widx];
        const unsigned long long* xp0 = (const unsigned long long*)(xs + r0);
        unsigned long long x0 = xp0[0], x1 = xp0[1], x2 = xp0[2], x3 = xp0[3];

        #pragma unroll 2
        for (int k = 0; k < K1; k++) {
            float4 wc = wb;
            if (k + 2 < K1) wc = W1v[(k + 2) * (HH / 4) + widx];
            unsigned long long y0 = x0, y1 = x1, y2 = x2, y3 = x3;
            if (k + 1 < K1) {
                const unsigned long long* xq =
                    (const unsigned long long*)(xs + (k + 1) * XSTR + r0);
                y0 = xq[0]; y1 = xq[1]; y2 = xq[2]; y3 = xq[3];
            }
            unsigned long long wd;
            wd = pack2(wa.x); fma2(acc[0], wd, x0);  fma2(acc[1], wd, x1);  fma2(acc[2], wd, x2);  fma2(acc[3], wd, x3);
            wd = pack2(wa.y); fma2(acc[4], wd, x0);  fma2(acc[5], wd, x1);  fma2(acc[6], wd, x2);  fma2(acc[7], wd, x3);
            wd = pack2(wa.z); fma2(acc[8], wd, x0);  fma2(acc[9], wd, x1);  fma2(acc[10], wd, x2); fma2(acc[11], wd, x3);
            wd = pack2(wa.w); fma2(acc[12], wd, x0); fma2(acc[13], wd, x1); fma2(acc[14], wd, x2); fma2(acc[15], wd, x3);
            wa = wb; wb = wc;
            x0 = y0; x1 = y1; x2 = y2; x3 = y3;
        }

        #pragma unroll
        for (int ci = 0; ci < 4; ci++) {
            int c = c0 + ci;
            float bias = B1[c];
            #pragma unroll
            for (int rp = 0; rp < 4; rp++) {
                float2 f = unpack2(acc[ci * 4 + rp]);
                hs[c * XSTR + r0 + rp * 2]     = gelu_exact(f.x + bias);
                hs[c * XSTR + r0 + rp * 2 + 1] = gelu_exact(f.y + bias);
            }
        }
    }
    __syncthreads();

    // ---- GEMM2: y = h @ W2 + b2, 2 cols x 8 rows per thread ----
    {
        int c0 = cg * 2, r0 = rg * 8;
        unsigned long long acc[8];
        #pragma unroll
        for (int z = 0; z < 8; z++) acc[z] = 0ULL;

        const float2* W2v = (const float2*)W2;   // [k][D/2]
        int widx = c0 >> 1;

        float2 wa = W2v[widx];
        float2 wb = W2v[(D / 2) + widx];
        const unsigned long long* hp0 = (const unsigned long long*)(hs + r0);
        unsigned long long x0 = hp0[0], x1 = hp0[1], x2 = hp0[2], x3 = hp0[3];

        #pragma unroll 2
        for (int k = 0; k < HH; k++) {
            float2 wc = wb;
            if (k + 2 < HH) wc = W2v[(k + 2) * (D / 2) + widx];
            unsigned long long y0 = x0, y1 = x1, y2 = x2, y3 = x3;
            if (k + 1 < HH) {
                const unsigned long long* hq =
                    (const unsigned long long*)(hs + (k + 1) * XSTR + r0);
                y0 = hq[0]; y1 = hq[1]; y2 = hq[2]; y3 = hq[3];
            }
            unsigned long long wd;
            wd = pack2(wa.x); fma2(acc[0], wd, x0); fma2(acc[1], wd, x1); fma2(acc[2], wd, x2); fma2(acc[3], wd, x3);
            wd = pack2(wa.y); fma2(acc[4], wd, x0); fma2(acc[5], wd, x1); fma2(acc[6], wd, x2); fma2(acc[7], wd, x3);
            wa = wb; wb = wc;
            x0 = y0; x1 = y1; x2 = y2; x3 = y3;
        }
        __syncthreads();   // all GEMM2 reads of hs done before zbuf overwrite

        // residual into zbuf (reuse hs)
        #pragma unroll
        for (int ci = 0; ci < 2; ci++) {
            int c = c0 + ci;
            float bias = B2[c];
            #pragma unroll
            for (int rp = 0; rp < 4; rp++) {
                float2 f = unpack2(acc[ci * 4 + rp]);
                int m0 = r0 + rp * 2;
                float le0 = xs[(256 + c) * XSTR + m0];
                float le1 = xs[(256 + c) * XSTR + m0 + 1];
                float re0 = xs[(512 + c) * XSTR + m0];
                float re1 = xs[(512 + c) * XSTR + m0 + 1];
                float z0, z1;
                if (tern) {
                    float te0 = xs[(768 + c) * XSTR + m0];
                    float te1 = xs[(768 + c) * XSTR + m0 + 1];
                    z0 = f.x + bias + (le0 + re0 + te0) / 3.0f;
                    z1 = f.y + bias + (le1 + re1 + te1) / 3.0f;
                } else {
                    z0 = f.x + bias + le0 + re0;
                    z1 = f.y + bias + le1 + re1;
                }
                hs[c * XSTR + m0]     = z0;
                hs[c * XSTR + m0 + 1] = z1;
            }
        }
    }
    __syncthreads();

    // ---- LayerNorm + write out (16 warps x 2 rows) ----
    {
        int wid = t >> 5, lane = t & 31;
        #pragma unroll
        for (int mi = 0; mi < 2; mi++) {
            int m = wid * 2 + mi;
            float v[8];
            float s = 0.0f, s2 = 0.0f;
            #pragma unroll
            for (int j = 0; j < 8; j++) {
                int c = lane + 32 * j;
                v[j] = hs[c * XSTR + m];
                s += v[j];
                s2 += v[j] * v[j];
            }
            #pragma unroll
            for (int off = 16; off > 0; off >>= 1) {
                s  += __shfl_xor_sync(0xFFFFFFFFu, s, off);
                s2 += __shfl_xor_sync(0xFFFFFFFFu, s2, off);
            }
            float mu = s * (1.0f / 256.0f);
            float var = s2 * (1.0f / 256.0f) - mu * mu;
            float rs = rsqrtf(var + 1e-5f);
            if (meta[64 + m]) {
                int node = meta[m];
                int i = meta[32 + m];
                float* outp = final_out ? (final_out + i * D) : (g_embeds + node * D);
                #pragma unroll
                for (int j = 0; j < 8; j++) {
                    int c = lane + 32 * j;
                    outp[c] = (v[j] - mu) * rs * gma[c] + bta[c];
                }
            }
        }
    }
}

// ---------------- launcher ----------------
extern "C" void kernel_launch(void* const* d_in, const int* in_sizes, int n_in,
                              void* d_out, int out_size) {
    const int*   comp_ids   = (const int*)d_in[0];
    const int*   op_ids     = (const int*)d_in[1];
    const int*   lc         = (const int*)d_in[2];
    const int*   rc         = (const int*)d_in[3];
    const int*   tc         = (const int*)d_in[4];
    const int*   l2         = (const int*)d_in[5];
    const int*   l1         = (const int*)d_in[6];
    const int*   l0         = (const int*)d_in[7];
    const float* comp_table = (const float*)d_in[8];
    const float* op_table   = (const float*)d_in[9];
    const float* W1b        = (const float*)d_in[10];
    const float* b1b        = (const float*)d_in[11];
    const float* W2b        = (const float*)d_in[12];
    const float* b2b        = (const float*)d_in[13];
    const float* W1t        = (const float*)d_in[14];
    const float* b1t        = (const float*)d_in[15];
    const float* W2t        = (const float*)d_in[16];
    const float* b2t        = (const float*)d_in[17];
    const float* gma        = (const float*)d_in[18];
    const float* bta        = (const float*)d_in[19];

    int n_nodes = in_sizes[0];
    int n2 = in_sizes[5], n1 = in_sizes[6], n0 = in_sizes[7];

    cudaFuncSetAttribute(level_kernel, cudaFuncAttributeMaxDynamicSharedMemorySize,
                         SMEM_BYTES);

    init_embeds_kernel<<<n_nodes, D>>>(comp_ids, comp_table);
    reset_kernel<<<1, 32>>>();
    int tot = n2 + n1 + n0;
    compact_kernel<<<(tot + 255) / 256, 256>>>(l2, n2, l1, n1, l0, n0, tc);

    int nb2 = (n2 + MT - 1) / MT;
    level_kernel<<<2 * nb2, NTHREADS, SMEM_BYTES>>>(
        nb2, 0, l2, lc, rc, tc, op_ids, op_table,
        W1b, b1b, W2b, b2b, W1t, b1t, W2t, b2t, gma, bta, nullptr);

    int nb1 = (n1 + MT - 1) / MT;
    level_kernel<<<2 * nb1, NTHREADS, SMEM_BYTES>>>(
        nb1, 1, l1, lc, rc, tc, op_ids, op_table,
        W1b, b1b, W2b, b2b, W1t, b1t, W2t, b2t, gma, bta, nullptr);

    int nb0 = (n0 + MT - 1) / MT;
    level_kernel<<<2 * nb0, NTHREADS, SMEM_BYTES>>>(
        nb0, 2, l0, lc, rc, tc, op_ids, op_table,
        W1b, b1b, W2b, b2b, W1t, b1t, W2t, b2t, gma, bta, (float*)d_out);
}